// round 2
// baseline (speedup 1.0000x reference)
#include <cuda_runtime.h>
#include <cuda_bf16.h>
#include <math.h>

// ---------------------------------------------------------------------------
// GNN_11957188952096: pre-linear -> SAGE(32->64) -> SAGE(64->64) -> pool -> MLP
// N=100000 nodes, E=1600000 edges, G=512 graphs
// ---------------------------------------------------------------------------

#define MAXN 100000
#define MAXG 512

// scratch (static device globals -- allocation-free)
__device__ float g_h0[MAXN * 32];     // pre-linear output
__device__ float g_h1[MAXN * 64];     // conv1 output
__device__ float g_agg32[MAXN * 32];  // conv1 neighbor sums
__device__ float g_agg64[MAXN * 64];  // conv2 neighbor sums
__device__ float g_cnt[MAXN];         // in-degree (shared by both convs)
__device__ float g_gsum[MAXG * 64];   // pooled sums
__device__ float g_gcnt[MAXG];        // nodes per graph

// ---------------------------------------------------------------------------
__global__ void zero_all(int N) {
    int i = blockIdx.x * blockDim.x + threadIdx.x;
    int stride = gridDim.x * blockDim.x;
    for (int k = i; k < N * 32; k += stride) g_agg32[k] = 0.f;
    for (int k = i; k < N * 64; k += stride) g_agg64[k] = 0.f;
    for (int k = i; k < N; k += stride) g_cnt[k] = 0.f;
    for (int k = i; k < MAXG * 64; k += stride) g_gsum[k] = 0.f;
    for (int k = i; k < MAXG; k += stride) g_gcnt[k] = 0.f;
}

// h0 = relu(x @ pre_w + pre_b)   x:[N,5]  pre_w:[5,32]
__global__ void pre_kernel(const float* __restrict__ x,
                           const float* __restrict__ w,
                           const float* __restrict__ b, int N) {
    __shared__ float sw[5 * 32];
    __shared__ float sb[32];
    for (int i = threadIdx.x; i < 160; i += blockDim.x) sw[i] = w[i];
    if (threadIdx.x < 32) sb[threadIdx.x] = b[threadIdx.x];
    __syncthreads();
    int n = blockIdx.x * blockDim.x + threadIdx.x;
    if (n >= N) return;
    float xv[5];
#pragma unroll
    for (int k = 0; k < 5; k++) xv[k] = x[n * 5 + k];
#pragma unroll
    for (int j = 0; j < 32; j++) {
        float acc = sb[j];
#pragma unroll
        for (int k = 0; k < 5; k++) acc = fmaf(xv[k], sw[k * 32 + j], acc);
        g_h0[n * 32 + j] = fmaxf(acc, 0.f);
    }
}

// in-degree counts (used by both convs)
__global__ void count_kernel(const int* __restrict__ dst, int E) {
    int e = blockIdx.x * blockDim.x + threadIdx.x;
    if (e < E) atomicAdd(&g_cnt[dst[e]], 1.f);
}

// scatter conv1: agg32[dst] += h0[src]   (8 threads per edge, float4 each)
__global__ void scatter32(const int* __restrict__ src, const int* __restrict__ dst,
                          long long total) {
    long long idx = (long long)blockIdx.x * blockDim.x + threadIdx.x;
    if (idx >= total) return;
    int e = (int)(idx >> 3);
    int q = (int)(idx & 7);
    int s = src[e];
    int d = dst[e];
    float4 v = reinterpret_cast<const float4*>(g_h0)[s * 8 + q];
    float* base = &g_agg32[d * 32 + q * 4];
    atomicAdd(base + 0, v.x);
    atomicAdd(base + 1, v.y);
    atomicAdd(base + 2, v.z);
    atomicAdd(base + 3, v.w);
}

// conv1 combine: h1 = relu(l2norm(mean_agg @ Wl + bl + h0 @ Wr))
// warp per node; lane holds input-dim "lane"; lane computes out dims lane, lane+32
__global__ void combine1(const float* __restrict__ wl, const float* __restrict__ bl,
                         const float* __restrict__ wr, int N) {
    __shared__ float swl[32 * 64];
    __shared__ float swr[32 * 64];
    __shared__ float sbl[64];
    for (int i = threadIdx.x; i < 32 * 64; i += blockDim.x) {
        swl[i] = wl[i];
        swr[i] = wr[i];
    }
    if (threadIdx.x < 64) sbl[threadIdx.x] = bl[threadIdx.x];
    __syncthreads();

    int n = (blockIdx.x * blockDim.x + threadIdx.x) >> 5;
    int lane = threadIdx.x & 31;
    if (n >= N) return;

    float c = g_cnt[n];
    float inv_c = c > 0.f ? 1.f / c : 0.f;
    float aggv = g_agg32[n * 32 + lane] * inv_c;
    float hv = g_h0[n * 32 + lane];

    float acc0 = sbl[lane];
    float acc1 = sbl[lane + 32];
#pragma unroll
    for (int l = 0; l < 32; l++) {
        float a = __shfl_sync(0xffffffffu, aggv, l);
        float h = __shfl_sync(0xffffffffu, hv, l);
        acc0 = fmaf(a, swl[l * 64 + lane], acc0);
        acc0 = fmaf(h, swr[l * 64 + lane], acc0);
        acc1 = fmaf(a, swl[l * 64 + lane + 32], acc1);
        acc1 = fmaf(h, swr[l * 64 + lane + 32], acc1);
    }
    float ss = acc0 * acc0 + acc1 * acc1;
#pragma unroll
    for (int o = 16; o > 0; o >>= 1) ss += __shfl_xor_sync(0xffffffffu, ss, o);
    float inv = 1.f / fmaxf(sqrtf(ss), 1e-12f);
    g_h1[n * 64 + lane] = fmaxf(acc0 * inv, 0.f);
    g_h1[n * 64 + lane + 32] = fmaxf(acc1 * inv, 0.f);
}

// scatter conv2: agg64[dst] += h1[src]   (16 threads per edge, float4 each)
__global__ void scatter64(const int* __restrict__ src, const int* __restrict__ dst,
                          long long total) {
    long long idx = (long long)blockIdx.x * blockDim.x + threadIdx.x;
    if (idx >= total) return;
    int e = (int)(idx >> 4);
    int q = (int)(idx & 15);
    int s = src[e];
    int d = dst[e];
    float4 v = reinterpret_cast<const float4*>(g_h1)[s * 16 + q];
    float* base = &g_agg64[d * 64 + q * 4];
    atomicAdd(base + 0, v.x);
    atomicAdd(base + 1, v.y);
    atomicAdd(base + 2, v.z);
    atomicAdd(base + 3, v.w);
}

// conv2 combine + global pooling (h2 never stored)
__global__ void combine2_pool(const int* __restrict__ batch,
                              const float* __restrict__ wl, const float* __restrict__ bl,
                              const float* __restrict__ wr, int N) {
    __shared__ float swl[64 * 64];
    __shared__ float swr[64 * 64];
    __shared__ float sbl[64];
    for (int i = threadIdx.x; i < 64 * 64; i += blockDim.x) {
        swl[i] = wl[i];
        swr[i] = wr[i];
    }
    if (threadIdx.x < 64) sbl[threadIdx.x] = bl[threadIdx.x];
    __syncthreads();

    int n = (blockIdx.x * blockDim.x + threadIdx.x) >> 5;
    int lane = threadIdx.x & 31;
    if (n >= N) return;

    float c = g_cnt[n];
    float inv_c = c > 0.f ? 1.f / c : 0.f;
    float a0 = g_agg64[n * 64 + lane] * inv_c;
    float a1 = g_agg64[n * 64 + 32 + lane] * inv_c;
    float h0 = g_h1[n * 64 + lane];
    float h1 = g_h1[n * 64 + 32 + lane];

    float acc0 = sbl[lane];
    float acc1 = sbl[lane + 32];
#pragma unroll
    for (int l = 0; l < 32; l++) {
        float b0 = __shfl_sync(0xffffffffu, a0, l);
        float b1 = __shfl_sync(0xffffffffu, a1, l);
        float c0 = __shfl_sync(0xffffffffu, h0, l);
        float c1 = __shfl_sync(0xffffffffu, h1, l);
        acc0 = fmaf(b0, swl[l * 64 + lane], acc0);
        acc0 = fmaf(b1, swl[(l + 32) * 64 + lane], acc0);
        acc0 = fmaf(c0, swr[l * 64 + lane], acc0);
        acc0 = fmaf(c1, swr[(l + 32) * 64 + lane], acc0);
        acc1 = fmaf(b0, swl[l * 64 + lane + 32], acc1);
        acc1 = fmaf(b1, swl[(l + 32) * 64 + lane + 32], acc1);
        acc1 = fmaf(c0, swr[l * 64 + lane + 32], acc1);
        acc1 = fmaf(c1, swr[(l + 32) * 64 + lane + 32], acc1);
    }
    float ss = acc0 * acc0 + acc1 * acc1;
#pragma unroll
    for (int o = 16; o > 0; o >>= 1) ss += __shfl_xor_sync(0xffffffffu, ss, o);
    float inv = 1.f / fmaxf(sqrtf(ss), 1e-12f);
    float v0 = fmaxf(acc0 * inv, 0.f);
    float v1 = fmaxf(acc1 * inv, 0.f);

    int b = batch[n];
    atomicAdd(&g_gsum[b * 64 + lane], v0);
    atomicAdd(&g_gsum[b * 64 + 32 + lane], v1);
    if (lane == 0) atomicAdd(&g_gcnt[b], 1.f);
}

// head: g = gsum/max(gcnt,1); relu(g@p1+b); relu(.@p2+b); .@o + b
__global__ void head_kernel(const float* __restrict__ p1w, const float* __restrict__ p1b,
                            const float* __restrict__ p2w, const float* __restrict__ p2b,
                            const float* __restrict__ ow, const float* __restrict__ ob,
                            float* __restrict__ out) {
    int g = blockIdx.x;  // 512 blocks x 64 threads
    int t = threadIdx.x;
    __shared__ float sg[64];
    __shared__ float sh[64];
    __shared__ float s2[16];

    float c = g_gcnt[g];
    float invc = 1.f / fmaxf(c, 1.f);
    sg[t] = g_gsum[g * 64 + t] * invc;
    __syncthreads();

    float acc = p1b[t];
#pragma unroll 8
    for (int k = 0; k < 64; k++) acc = fmaf(sg[k], p1w[k * 64 + t], acc);
    sh[t] = fmaxf(acc, 0.f);
    __syncthreads();

    if (t < 16) {
        float a = p2b[t];
#pragma unroll 8
        for (int k = 0; k < 64; k++) a = fmaf(sh[k], p2w[k * 16 + t], a);
        s2[t] = fmaxf(a, 0.f);
    }
    __syncthreads();

    if (t == 0) {
        float a = ob[0];
#pragma unroll
        for (int k = 0; k < 16; k++) a = fmaf(s2[k], ow[k], a);
        out[g] = a;
    }
}

// ---------------------------------------------------------------------------
extern "C" void kernel_launch(void* const* d_in, const int* in_sizes, int n_in,
                              void* d_out, int out_size) {
    const float* x = (const float*)d_in[0];
    const int* ei = (const int*)d_in[1];
    const int* batch = (const int*)d_in[2];

    // weights are the last 14 inputs (robust to whether num_graphs scalar is passed)
    int base = n_in - 14;
    const float* pre_w = (const float*)d_in[base + 0];
    const float* pre_b = (const float*)d_in[base + 1];
    const float* c1_wl = (const float*)d_in[base + 2];
    const float* c1_bl = (const float*)d_in[base + 3];
    const float* c1_wr = (const float*)d_in[base + 4];
    const float* c2_wl = (const float*)d_in[base + 5];
    const float* c2_bl = (const float*)d_in[base + 6];
    const float* c2_wr = (const float*)d_in[base + 7];
    const float* p1_w = (const float*)d_in[base + 8];
    const float* p1_b = (const float*)d_in[base + 9];
    const float* p2_w = (const float*)d_in[base + 10];
    const float* p2_b = (const float*)d_in[base + 11];
    const float* o_w = (const float*)d_in[base + 12];
    const float* o_b = (const float*)d_in[base + 13];

    int N = in_sizes[0] / 5;
    int E = in_sizes[1] / 2;
    const int* src = ei;
    const int* dst = ei + E;
    float* out = (float*)d_out;

    // 1. zero scratch
    zero_all<<<2048, 256>>>(N);

    // 2. pre-linear
    pre_kernel<<<(N + 255) / 256, 256>>>(x, pre_w, pre_b, N);

    // 3. degree counts
    count_kernel<<<(E + 255) / 256, 256>>>(dst, E);

    // 4. conv1 scatter (E*8 threads)
    {
        long long total = (long long)E * 8;
        int blocks = (int)((total + 255) / 256);
        scatter32<<<blocks, 256>>>(src, dst, total);
    }

    // 5. conv1 combine (warp per node)
    combine1<<<(N * 32 + 255) / 256, 256>>>(c1_wl, c1_bl, c1_wr, N);

    // 6. conv2 scatter (E*16 threads)
    {
        long long total = (long long)E * 16;
        int blocks = (int)((total + 255) / 256);
        scatter64<<<blocks, 256>>>(src, dst, total);
    }

    // 7. conv2 combine + pool (warp per node)
    combine2_pool<<<(N * 32 + 255) / 256, 256>>>(batch, c2_wl, c2_bl, c2_wr, N);

    // 8. head
    head_kernel<<<out_size, 64>>>(p1_w, p1_b, p2_w, p2_b, o_w, o_b, out);
}

// round 3
// speedup vs baseline: 1.4456x; 1.4456x over previous
#include <cuda_runtime.h>
#include <cuda_bf16.h>
#include <math.h>

// ---------------------------------------------------------------------------
// GNN_11957188952096: pre-linear -> SAGE(32->64) -> SAGE(64->64) -> pool -> MLP
// N=100000 nodes, E=1600000 edges, G=512 graphs
// ---------------------------------------------------------------------------

#define MAXN 100000
#define MAXG 512

// scratch (static device globals -- allocation-free)
__device__ float g_h0[MAXN * 32];     // pre-linear output
__device__ float g_h1[MAXN * 64];     // conv1 output
__device__ float g_agg32[MAXN * 32];  // conv1 neighbor sums
__device__ float g_agg64[MAXN * 64];  // conv2 neighbor sums
__device__ float g_cnt[MAXN];         // in-degree (shared by both convs)
__device__ float g_gsum[MAXG * 64];   // pooled sums
__device__ float g_gcnt[MAXG];        // nodes per graph

// vector reduction: one L1tex wavefront instead of four scalar atomics
__device__ __forceinline__ void red_add_v4(float* addr, float4 v) {
    asm volatile("red.global.add.v4.f32 [%0], {%1, %2, %3, %4};"
                 :: "l"(addr), "f"(v.x), "f"(v.y), "f"(v.z), "f"(v.w)
                 : "memory");
}

__device__ __forceinline__ void red_add_f32(float* addr, float v) {
    asm volatile("red.global.add.f32 [%0], %1;"
                 :: "l"(addr), "f"(v) : "memory");
}

// ---------------------------------------------------------------------------
__global__ void zero_all(int N) {
    int i = blockIdx.x * blockDim.x + threadIdx.x;
    int stride = gridDim.x * blockDim.x;
    for (int k = i; k < N * 32; k += stride) g_agg32[k] = 0.f;
    for (int k = i; k < N * 64; k += stride) g_agg64[k] = 0.f;
    for (int k = i; k < N; k += stride) g_cnt[k] = 0.f;
    for (int k = i; k < MAXG * 64; k += stride) g_gsum[k] = 0.f;
    for (int k = i; k < MAXG; k += stride) g_gcnt[k] = 0.f;
}

// h0 = relu(x @ pre_w + pre_b)   x:[N,5]  pre_w:[5,32]
__global__ void pre_kernel(const float* __restrict__ x,
                           const float* __restrict__ w,
                           const float* __restrict__ b, int N) {
    __shared__ float sw[5 * 32];
    __shared__ float sb[32];
    for (int i = threadIdx.x; i < 160; i += blockDim.x) sw[i] = w[i];
    if (threadIdx.x < 32) sb[threadIdx.x] = b[threadIdx.x];
    __syncthreads();
    int n = blockIdx.x * blockDim.x + threadIdx.x;
    if (n >= N) return;
    float xv[5];
#pragma unroll
    for (int k = 0; k < 5; k++) xv[k] = x[n * 5 + k];
#pragma unroll
    for (int j = 0; j < 32; j++) {
        float acc = sb[j];
#pragma unroll
        for (int k = 0; k < 5; k++) acc = fmaf(xv[k], sw[k * 32 + j], acc);
        g_h0[n * 32 + j] = fmaxf(acc, 0.f);
    }
}

// scatter conv1 + degree count: agg32[dst] += h0[src]; cnt[dst] += 1
// 8 threads per edge, one float4 gather + one red.v4 each
__global__ void scatter32(const int* __restrict__ src, const int* __restrict__ dst,
                          long long total) {
    long long idx = (long long)blockIdx.x * blockDim.x + threadIdx.x;
    if (idx >= total) return;
    int e = (int)(idx >> 3);
    int q = (int)(idx & 7);
    int s = __ldg(&src[e]);
    int d = __ldg(&dst[e]);
    float4 v = reinterpret_cast<const float4*>(g_h0)[s * 8 + q];
    red_add_v4(&g_agg32[d * 32 + q * 4], v);
    if (q == 0) red_add_f32(&g_cnt[d], 1.f);
}

// conv1 combine: h1 = relu(l2norm(mean_agg @ Wl + bl + h0 @ Wr))
// warp per node; 1024-thread blocks amortize the weight smem load 4x
__global__ __launch_bounds__(1024)
void combine1(const float* __restrict__ wl, const float* __restrict__ bl,
              const float* __restrict__ wr, int N) {
    __shared__ float swl[32 * 64];
    __shared__ float swr[32 * 64];
    __shared__ float sbl[64];
    for (int i = threadIdx.x; i < 32 * 64; i += blockDim.x) {
        swl[i] = wl[i];
        swr[i] = wr[i];
    }
    if (threadIdx.x < 64) sbl[threadIdx.x] = bl[threadIdx.x];
    __syncthreads();

    int n = (blockIdx.x * blockDim.x + threadIdx.x) >> 5;
    int lane = threadIdx.x & 31;
    if (n >= N) return;

    float c = g_cnt[n];
    float inv_c = c > 0.f ? 1.f / c : 0.f;
    float aggv = g_agg32[n * 32 + lane] * inv_c;
    float hv = g_h0[n * 32 + lane];

    float acc0 = sbl[lane];
    float acc1 = sbl[lane + 32];
#pragma unroll
    for (int l = 0; l < 32; l++) {
        float a = __shfl_sync(0xffffffffu, aggv, l);
        float h = __shfl_sync(0xffffffffu, hv, l);
        acc0 = fmaf(a, swl[l * 64 + lane], acc0);
        acc0 = fmaf(h, swr[l * 64 + lane], acc0);
        acc1 = fmaf(a, swl[l * 64 + lane + 32], acc1);
        acc1 = fmaf(h, swr[l * 64 + lane + 32], acc1);
    }
    float ss = acc0 * acc0 + acc1 * acc1;
#pragma unroll
    for (int o = 16; o > 0; o >>= 1) ss += __shfl_xor_sync(0xffffffffu, ss, o);
    float inv = 1.f / fmaxf(sqrtf(ss), 1e-12f);
    g_h1[n * 64 + lane] = fmaxf(acc0 * inv, 0.f);
    g_h1[n * 64 + lane + 32] = fmaxf(acc1 * inv, 0.f);
}

// scatter conv2: agg64[dst] += h1[src]   (16 threads per edge, red.v4 each)
__global__ void scatter64(const int* __restrict__ src, const int* __restrict__ dst,
                          long long total) {
    long long idx = (long long)blockIdx.x * blockDim.x + threadIdx.x;
    if (idx >= total) return;
    int e = (int)(idx >> 4);
    int q = (int)(idx & 15);
    int s = __ldg(&src[e]);
    int d = __ldg(&dst[e]);
    float4 v = reinterpret_cast<const float4*>(g_h1)[s * 16 + q];
    red_add_v4(&g_agg64[d * 64 + q * 4], v);
}

// conv2 combine + global pooling (h2 never stored)
__global__ __launch_bounds__(1024)
void combine2_pool(const int* __restrict__ batch,
                   const float* __restrict__ wl, const float* __restrict__ bl,
                   const float* __restrict__ wr, int N) {
    __shared__ float swl[64 * 64];
    __shared__ float swr[64 * 64];
    __shared__ float sbl[64];
    for (int i = threadIdx.x; i < 64 * 64; i += blockDim.x) {
        swl[i] = wl[i];
        swr[i] = wr[i];
    }
    if (threadIdx.x < 64) sbl[threadIdx.x] = bl[threadIdx.x];
    __syncthreads();

    int n = (blockIdx.x * blockDim.x + threadIdx.x) >> 5;
    int lane = threadIdx.x & 31;
    if (n >= N) return;

    float c = g_cnt[n];
    float inv_c = c > 0.f ? 1.f / c : 0.f;
    float a0 = g_agg64[n * 64 + lane] * inv_c;
    float a1 = g_agg64[n * 64 + 32 + lane] * inv_c;
    float h0 = g_h1[n * 64 + lane];
    float h1 = g_h1[n * 64 + 32 + lane];

    float acc0 = sbl[lane];
    float acc1 = sbl[lane + 32];
#pragma unroll
    for (int l = 0; l < 32; l++) {
        float b0 = __shfl_sync(0xffffffffu, a0, l);
        float b1 = __shfl_sync(0xffffffffu, a1, l);
        float c0 = __shfl_sync(0xffffffffu, h0, l);
        float c1 = __shfl_sync(0xffffffffu, h1, l);
        acc0 = fmaf(b0, swl[l * 64 + lane], acc0);
        acc0 = fmaf(b1, swl[(l + 32) * 64 + lane], acc0);
        acc0 = fmaf(c0, swr[l * 64 + lane], acc0);
        acc0 = fmaf(c1, swr[(l + 32) * 64 + lane], acc0);
        acc1 = fmaf(b0, swl[l * 64 + lane + 32], acc1);
        acc1 = fmaf(b1, swl[(l + 32) * 64 + lane + 32], acc1);
        acc1 = fmaf(c0, swr[l * 64 + lane + 32], acc1);
        acc1 = fmaf(c1, swr[(l + 32) * 64 + lane + 32], acc1);
    }
    float ss = acc0 * acc0 + acc1 * acc1;
#pragma unroll
    for (int o = 16; o > 0; o >>= 1) ss += __shfl_xor_sync(0xffffffffu, ss, o);
    float inv = 1.f / fmaxf(sqrtf(ss), 1e-12f);
    float v0 = fmaxf(acc0 * inv, 0.f);
    float v1 = fmaxf(acc1 * inv, 0.f);

    int b = batch[n];
    red_add_f32(&g_gsum[b * 64 + lane], v0);
    red_add_f32(&g_gsum[b * 64 + 32 + lane], v1);
    if (lane == 0) red_add_f32(&g_gcnt[b], 1.f);
}

// head: g = gsum/max(gcnt,1); relu(g@p1+b); relu(.@p2+b); .@o + b
__global__ void head_kernel(const float* __restrict__ p1w, const float* __restrict__ p1b,
                            const float* __restrict__ p2w, const float* __restrict__ p2b,
                            const float* __restrict__ ow, const float* __restrict__ ob,
                            float* __restrict__ out) {
    int g = blockIdx.x;  // 512 blocks x 64 threads
    int t = threadIdx.x;
    __shared__ float sg[64];
    __shared__ float sh[64];
    __shared__ float s2[16];

    float c = g_gcnt[g];
    float invc = 1.f / fmaxf(c, 1.f);
    sg[t] = g_gsum[g * 64 + t] * invc;
    __syncthreads();

    float acc = p1b[t];
#pragma unroll 8
    for (int k = 0; k < 64; k++) acc = fmaf(sg[k], p1w[k * 64 + t], acc);
    sh[t] = fmaxf(acc, 0.f);
    __syncthreads();

    if (t < 16) {
        float a = p2b[t];
#pragma unroll 8
        for (int k = 0; k < 64; k++) a = fmaf(sh[k], p2w[k * 16 + t], a);
        s2[t] = fmaxf(a, 0.f);
    }
    __syncthreads();

    if (t == 0) {
        float a = ob[0];
#pragma unroll
        for (int k = 0; k < 16; k++) a = fmaf(s2[k], ow[k], a);
        out[g] = a;
    }
}

// ---------------------------------------------------------------------------
extern "C" void kernel_launch(void* const* d_in, const int* in_sizes, int n_in,
                              void* d_out, int out_size) {
    const float* x = (const float*)d_in[0];
    const int* ei = (const int*)d_in[1];
    const int* batch = (const int*)d_in[2];

    // weights are the last 14 inputs
    int base = n_in - 14;
    const float* pre_w = (const float*)d_in[base + 0];
    const float* pre_b = (const float*)d_in[base + 1];
    const float* c1_wl = (const float*)d_in[base + 2];
    const float* c1_bl = (const float*)d_in[base + 3];
    const float* c1_wr = (const float*)d_in[base + 4];
    const float* c2_wl = (const float*)d_in[base + 5];
    const float* c2_bl = (const float*)d_in[base + 6];
    const float* c2_wr = (const float*)d_in[base + 7];
    const float* p1_w = (const float*)d_in[base + 8];
    const float* p1_b = (const float*)d_in[base + 9];
    const float* p2_w = (const float*)d_in[base + 10];
    const float* p2_b = (const float*)d_in[base + 11];
    const float* o_w = (const float*)d_in[base + 12];
    const float* o_b = (const float*)d_in[base + 13];

    int N = in_sizes[0] / 5;
    int E = in_sizes[1] / 2;
    const int* src = ei;
    const int* dst = ei + E;
    float* out = (float*)d_out;

    // 1. zero scratch
    zero_all<<<2048, 256>>>(N);

    // 2. pre-linear
    pre_kernel<<<(N + 255) / 256, 256>>>(x, pre_w, pre_b, N);

    // 3. conv1 scatter + degree count (E*8 threads)
    {
        long long total = (long long)E * 8;
        int blocks = (int)((total + 255) / 256);
        scatter32<<<blocks, 256>>>(src, dst, total);
    }

    // 4. conv1 combine (warp per node, 1024-thread blocks)
    combine1<<<(N * 32 + 1023) / 1024, 1024>>>(c1_wl, c1_bl, c1_wr, N);

    // 5. conv2 scatter (E*16 threads)
    {
        long long total = (long long)E * 16;
        int blocks = (int)((total + 255) / 256);
        scatter64<<<blocks, 256>>>(src, dst, total);
    }

    // 6. conv2 combine + pool (warp per node, 1024-thread blocks)
    combine2_pool<<<(N * 32 + 1023) / 1024, 1024>>>(batch, c2_wl, c2_bl, c2_wr, N);

    // 7. head
    head_kernel<<<out_size, 64>>>(p1_w, p1_b, p2_w, p2_b, o_w, o_b, out);
}

// round 4
// speedup vs baseline: 1.9065x; 1.3188x over previous
#include <cuda_runtime.h>
#include <cuda_bf16.h>
#include <math.h>

// ---------------------------------------------------------------------------
// GNN_11957188952096: pre-linear -> SAGE(32->64) -> SAGE(64->64) -> pool -> MLP
// N=100000 nodes, E=1600000 edges, G=512 graphs
// ---------------------------------------------------------------------------

#define MAXN 100000
#define MAXG 512

__device__ float g_h0[MAXN * 32];     // pre-linear output
__device__ float g_h1[MAXN * 64];     // conv1 output
__device__ float g_agg32[MAXN * 32];  // conv1 neighbor sums
__device__ float g_agg64[MAXN * 64];  // conv2 neighbor sums
__device__ float g_cnt[MAXN];         // in-degree
__device__ float g_gsum[MAXG * 64];   // pooled sums
__device__ float g_gcnt[MAXG];        // nodes per graph

__device__ __forceinline__ void red_add_v4(float* addr, float4 v) {
    asm volatile("red.global.add.v4.f32 [%0], {%1, %2, %3, %4};"
                 :: "l"(addr), "f"(v.x), "f"(v.y), "f"(v.z), "f"(v.w)
                 : "memory");
}
__device__ __forceinline__ void red_add_f32(float* addr, float v) {
    asm volatile("red.global.add.f32 [%0], %1;"
                 :: "l"(addr), "f"(v) : "memory");
}

// ---------------------------------------------------------------------------
__global__ void zero_all(int N) {
    int i = blockIdx.x * blockDim.x + threadIdx.x;
    int stride = gridDim.x * blockDim.x;
    for (int k = i; k < N * 32; k += stride) g_agg32[k] = 0.f;
    for (int k = i; k < N * 64; k += stride) g_agg64[k] = 0.f;
    for (int k = i; k < N; k += stride) g_cnt[k] = 0.f;
    for (int k = i; k < MAXG * 64; k += stride) g_gsum[k] = 0.f;
    for (int k = i; k < MAXG; k += stride) g_gcnt[k] = 0.f;
}

// h0 = relu(x @ pre_w + pre_b)
__global__ void pre_kernel(const float* __restrict__ x,
                           const float* __restrict__ w,
                           const float* __restrict__ b, int N) {
    __shared__ float sw[5 * 32];
    __shared__ float sb[32];
    for (int i = threadIdx.x; i < 160; i += blockDim.x) sw[i] = w[i];
    if (threadIdx.x < 32) sb[threadIdx.x] = b[threadIdx.x];
    __syncthreads();
    int n = blockIdx.x * blockDim.x + threadIdx.x;
    if (n >= N) return;
    float xv[5];
#pragma unroll
    for (int k = 0; k < 5; k++) xv[k] = x[n * 5 + k];
#pragma unroll
    for (int j = 0; j < 32; j++) {
        float acc = sb[j];
#pragma unroll
        for (int k = 0; k < 5; k++) acc = fmaf(xv[k], sw[k * 32 + j], acc);
        g_h0[n * 32 + j] = fmaxf(acc, 0.f);
    }
}

// scatter conv1 + degree count (8 threads/edge, red.v4)
__global__ void scatter32(const int* __restrict__ src, const int* __restrict__ dst,
                          long long total) {
    long long idx = (long long)blockIdx.x * blockDim.x + threadIdx.x;
    if (idx >= total) return;
    int e = (int)(idx >> 3);
    int q = (int)(idx & 7);
    int s = __ldg(&src[e]);
    int d = __ldg(&dst[e]);
    float4 v = reinterpret_cast<const float4*>(g_h0)[s * 8 + q];
    red_add_v4(&g_agg32[d * 32 + q * 4], v);
    if (q == 0) red_add_f32(&g_cnt[d], 1.f);
}

// conv1 combine: h1 = relu(l2norm(mean_agg @ Wl + bl + h0 @ Wr))
// 4 nodes per warp; weight cols (j, j+32) paired as float2 in smem
__global__ __launch_bounds__(1024)
void combine1(const float* __restrict__ wl, const float* __restrict__ bl,
              const float* __restrict__ wr, int N) {
    __shared__ float2 swl[32 * 32];   // [l][j] = (wl[l,j], wl[l,j+32])
    __shared__ float2 swr[32 * 32];
    __shared__ float sbl[64];
    for (int i = threadIdx.x; i < 32 * 32; i += blockDim.x) {
        int l = i >> 5, j = i & 31;
        swl[i] = make_float2(wl[l * 64 + j], wl[l * 64 + j + 32]);
        swr[i] = make_float2(wr[l * 64 + j], wr[l * 64 + j + 32]);
    }
    if (threadIdx.x < 64) sbl[threadIdx.x] = bl[threadIdx.x];
    __syncthreads();

    int warp = (blockIdx.x * blockDim.x + threadIdx.x) >> 5;
    int lane = threadIdx.x & 31;
    int n0 = warp * 4;
    if (n0 >= N) return;

    float aggv[4], hv[4], acc0[4], acc1[4];
#pragma unroll
    for (int i = 0; i < 4; i++) {
        int n = n0 + i;
        if (n < N) {
            float c = g_cnt[n];
            float inv_c = c > 0.f ? 1.f / c : 0.f;
            aggv[i] = g_agg32[n * 32 + lane] * inv_c;
            hv[i] = g_h0[n * 32 + lane];
        } else {
            aggv[i] = 0.f; hv[i] = 0.f;
        }
        acc0[i] = sbl[lane];
        acc1[i] = sbl[lane + 32];
    }

#pragma unroll
    for (int l = 0; l < 32; l++) {
        float2 wlp = swl[l * 32 + lane];
        float2 wrp = swr[l * 32 + lane];
#pragma unroll
        for (int i = 0; i < 4; i++) {
            float a = __shfl_sync(0xffffffffu, aggv[i], l);
            float h = __shfl_sync(0xffffffffu, hv[i], l);
            acc0[i] = fmaf(a, wlp.x, acc0[i]);
            acc0[i] = fmaf(h, wrp.x, acc0[i]);
            acc1[i] = fmaf(a, wlp.y, acc1[i]);
            acc1[i] = fmaf(h, wrp.y, acc1[i]);
        }
    }

#pragma unroll
    for (int i = 0; i < 4; i++) {
        int n = n0 + i;
        if (n >= N) break;
        float ss = acc0[i] * acc0[i] + acc1[i] * acc1[i];
#pragma unroll
        for (int o = 16; o > 0; o >>= 1) ss += __shfl_xor_sync(0xffffffffu, ss, o);
        float inv = 1.f / fmaxf(sqrtf(ss), 1e-12f);
        g_h1[n * 64 + lane] = fmaxf(acc0[i] * inv, 0.f);
        g_h1[n * 64 + lane + 32] = fmaxf(acc1[i] * inv, 0.f);
    }
}

// scatter conv2 (16 threads/edge, red.v4)
__global__ void scatter64(const int* __restrict__ src, const int* __restrict__ dst,
                          long long total) {
    long long idx = (long long)blockIdx.x * blockDim.x + threadIdx.x;
    if (idx >= total) return;
    int e = (int)(idx >> 4);
    int q = (int)(idx & 15);
    int s = __ldg(&src[e]);
    int d = __ldg(&dst[e]);
    float4 v = reinterpret_cast<const float4*>(g_h1)[s * 16 + q];
    red_add_v4(&g_agg64[d * 64 + q * 4], v);
}

// conv2 combine + pooling; 4 nodes per warp, paired weights
__global__ __launch_bounds__(1024)
void combine2_pool(const int* __restrict__ batch,
                   const float* __restrict__ wl, const float* __restrict__ bl,
                   const float* __restrict__ wr, int N) {
    __shared__ float2 swl[64 * 32];   // [l][j] = (wl[l,j], wl[l,j+32]), l in 0..63
    __shared__ float2 swr[64 * 32];
    __shared__ float sbl[64];
    for (int i = threadIdx.x; i < 64 * 32; i += blockDim.x) {
        int l = i >> 5, j = i & 31;
        swl[i] = make_float2(wl[l * 64 + j], wl[l * 64 + j + 32]);
        swr[i] = make_float2(wr[l * 64 + j], wr[l * 64 + j + 32]);
    }
    if (threadIdx.x < 64) sbl[threadIdx.x] = bl[threadIdx.x];
    __syncthreads();

    int warp = (blockIdx.x * blockDim.x + threadIdx.x) >> 5;
    int lane = threadIdx.x & 31;
    int n0 = warp * 4;
    if (n0 >= N) return;

    float a0[4], a1[4], h0[4], h1[4], acc0[4], acc1[4];
#pragma unroll
    for (int i = 0; i < 4; i++) {
        int n = n0 + i;
        if (n < N) {
            float c = g_cnt[n];
            float inv_c = c > 0.f ? 1.f / c : 0.f;
            a0[i] = g_agg64[n * 64 + lane] * inv_c;
            a1[i] = g_agg64[n * 64 + 32 + lane] * inv_c;
            h0[i] = g_h1[n * 64 + lane];
            h1[i] = g_h1[n * 64 + 32 + lane];
        } else {
            a0[i] = a1[i] = h0[i] = h1[i] = 0.f;
        }
        acc0[i] = sbl[lane];
        acc1[i] = sbl[lane + 32];
    }

#pragma unroll
    for (int l = 0; l < 32; l++) {
        float2 wlA = swl[l * 32 + lane];
        float2 wlB = swl[(l + 32) * 32 + lane];
        float2 wrA = swr[l * 32 + lane];
        float2 wrB = swr[(l + 32) * 32 + lane];
#pragma unroll
        for (int i = 0; i < 4; i++) {
            float b0 = __shfl_sync(0xffffffffu, a0[i], l);
            float b1 = __shfl_sync(0xffffffffu, a1[i], l);
            float c0 = __shfl_sync(0xffffffffu, h0[i], l);
            float c1 = __shfl_sync(0xffffffffu, h1[i], l);
            acc0[i] = fmaf(b0, wlA.x, acc0[i]);
            acc0[i] = fmaf(b1, wlB.x, acc0[i]);
            acc0[i] = fmaf(c0, wrA.x, acc0[i]);
            acc0[i] = fmaf(c1, wrB.x, acc0[i]);
            acc1[i] = fmaf(b0, wlA.y, acc1[i]);
            acc1[i] = fmaf(b1, wlB.y, acc1[i]);
            acc1[i] = fmaf(c0, wrA.y, acc1[i]);
            acc1[i] = fmaf(c1, wrB.y, acc1[i]);
        }
    }

#pragma unroll
    for (int i = 0; i < 4; i++) {
        int n = n0 + i;
        if (n >= N) break;
        float ss = acc0[i] * acc0[i] + acc1[i] * acc1[i];
#pragma unroll
        for (int o = 16; o > 0; o >>= 1) ss += __shfl_xor_sync(0xffffffffu, ss, o);
        float inv = 1.f / fmaxf(sqrtf(ss), 1e-12f);
        float v0 = fmaxf(acc0[i] * inv, 0.f);
        float v1 = fmaxf(acc1[i] * inv, 0.f);
        int b = batch[n];
        red_add_f32(&g_gsum[b * 64 + lane], v0);
        red_add_f32(&g_gsum[b * 64 + 32 + lane], v1);
        if (lane == 0) red_add_f32(&g_gcnt[b], 1.f);
    }
}

// head MLP
__global__ void head_kernel(const float* __restrict__ p1w, const float* __restrict__ p1b,
                            const float* __restrict__ p2w, const float* __restrict__ p2b,
                            const float* __restrict__ ow, const float* __restrict__ ob,
                            float* __restrict__ out) {
    int g = blockIdx.x;
    int t = threadIdx.x;
    __shared__ float sg[64];
    __shared__ float sh[64];
    __shared__ float s2[16];

    float c = g_gcnt[g];
    float invc = 1.f / fmaxf(c, 1.f);
    sg[t] = g_gsum[g * 64 + t] * invc;
    __syncthreads();

    float acc = p1b[t];
#pragma unroll 8
    for (int k = 0; k < 64; k++) acc = fmaf(sg[k], p1w[k * 64 + t], acc);
    sh[t] = fmaxf(acc, 0.f);
    __syncthreads();

    if (t < 16) {
        float a = p2b[t];
#pragma unroll 8
        for (int k = 0; k < 64; k++) a = fmaf(sh[k], p2w[k * 16 + t], a);
        s2[t] = fmaxf(a, 0.f);
    }
    __syncthreads();

    if (t == 0) {
        float a = ob[0];
#pragma unroll
        for (int k = 0; k < 16; k++) a = fmaf(s2[k], ow[k], a);
        out[g] = a;
    }
}

// ---------------------------------------------------------------------------
extern "C" void kernel_launch(void* const* d_in, const int* in_sizes, int n_in,
                              void* d_out, int out_size) {
    const float* x = (const float*)d_in[0];
    const int* ei = (const int*)d_in[1];
    const int* batch = (const int*)d_in[2];

    int base = n_in - 14;
    const float* pre_w = (const float*)d_in[base + 0];
    const float* pre_b = (const float*)d_in[base + 1];
    const float* c1_wl = (const float*)d_in[base + 2];
    const float* c1_bl = (const float*)d_in[base + 3];
    const float* c1_wr = (const float*)d_in[base + 4];
    const float* c2_wl = (const float*)d_in[base + 5];
    const float* c2_bl = (const float*)d_in[base + 6];
    const float* c2_wr = (const float*)d_in[base + 7];
    const float* p1_w = (const float*)d_in[base + 8];
    const float* p1_b = (const float*)d_in[base + 9];
    const float* p2_w = (const float*)d_in[base + 10];
    const float* p2_b = (const float*)d_in[base + 11];
    const float* o_w = (const float*)d_in[base + 12];
    const float* o_b = (const float*)d_in[base + 13];

    int N = in_sizes[0] / 5;
    int E = in_sizes[1] / 2;
    const int* src = ei;
    const int* dst = ei + E;
    float* out = (float*)d_out;

    zero_all<<<2048, 256>>>(N);
    pre_kernel<<<(N + 255) / 256, 256>>>(x, pre_w, pre_b, N);

    {
        long long total = (long long)E * 8;
        scatter32<<<(int)((total + 255) / 256), 256>>>(src, dst, total);
    }

    // 4 nodes per warp -> 128 nodes per 1024-thread block
    combine1<<<(N + 127) / 128, 1024>>>(c1_wl, c1_bl, c1_wr, N);

    {
        long long total = (long long)E * 16;
        scatter64<<<(int)((total + 255) / 256), 256>>>(src, dst, total);
    }

    combine2_pool<<<(N + 127) / 128, 1024>>>(batch, c2_wl, c2_bl, c2_wr, N);

    head_kernel<<<out_size, 64>>>(p1_w, p1_b, p2_w, p2_b, o_w, o_b, out);
}

// round 5
// speedup vs baseline: 2.0721x; 1.0868x over previous
#include <cuda_runtime.h>
#include <cuda_bf16.h>
#include <math.h>

// ---------------------------------------------------------------------------
// GNN_11957188952096: pre-linear -> SAGE(32->64) -> SAGE(64->64) -> pool -> MLP
// N=100000 nodes, E=1600000 edges, G=512 graphs
// ---------------------------------------------------------------------------

#define MAXN 100000
#define MAXG 512

__device__ float g_h0[MAXN * 32];     // pre-linear output
__device__ float g_h1[MAXN * 64];     // conv1 output
__device__ float g_agg32[MAXN * 32];  // conv1 neighbor sums
__device__ float g_agg64[MAXN * 64];  // conv2 neighbor sums
__device__ float g_cnt[MAXN];         // in-degree
__device__ float g_gsum[MAXG * 64];   // pooled sums
__device__ float g_gcnt[MAXG];        // nodes per graph

typedef unsigned long long ull;

__device__ __forceinline__ void red_add_v4(float* addr, float4 v) {
    asm volatile("red.global.add.v4.f32 [%0], {%1, %2, %3, %4};"
                 :: "l"(addr), "f"(v.x), "f"(v.y), "f"(v.z), "f"(v.w)
                 : "memory");
}
__device__ __forceinline__ void red_add_f32(float* addr, float v) {
    asm volatile("red.global.add.f32 [%0], %1;"
                 :: "l"(addr), "f"(v) : "memory");
}
// packed f32x2 fma: (d.lo,d.hi) = a*b + c elementwise
__device__ __forceinline__ ull ffma2(ull a, ull b, ull c) {
    ull d;
    asm("fma.rn.f32x2 %0, %1, %2, %3;" : "=l"(d) : "l"(a), "l"(b), "l"(c));
    return d;
}
__device__ __forceinline__ ull dup2(float x) {
    ull d;
    asm("mov.b64 %0, {%1, %1};" : "=l"(d) : "r"(__float_as_uint(x)));
    return d;
}
__device__ __forceinline__ float2 unpack2(ull v) {
    float2 r;
    asm("mov.b64 {%0, %1}, %2;" : "=f"(r.x), "=f"(r.y) : "l"(v));
    return r;
}

// ---------------------------------------------------------------------------
__global__ void zero_all(int N) {
    int i = blockIdx.x * blockDim.x + threadIdx.x;
    int stride = gridDim.x * blockDim.x;
    for (int k = i; k < N * 32; k += stride) g_agg32[k] = 0.f;
    for (int k = i; k < N * 64; k += stride) g_agg64[k] = 0.f;
    for (int k = i; k < N; k += stride) g_cnt[k] = 0.f;
    for (int k = i; k < MAXG * 64; k += stride) g_gsum[k] = 0.f;
    for (int k = i; k < MAXG; k += stride) g_gcnt[k] = 0.f;
}

// h0 = relu(x @ pre_w + pre_b)
__global__ void pre_kernel(const float* __restrict__ x,
                           const float* __restrict__ w,
                           const float* __restrict__ b, int N) {
    __shared__ float sw[5 * 32];
    __shared__ float sb[32];
    for (int i = threadIdx.x; i < 160; i += blockDim.x) sw[i] = w[i];
    if (threadIdx.x < 32) sb[threadIdx.x] = b[threadIdx.x];
    __syncthreads();
    int n = blockIdx.x * blockDim.x + threadIdx.x;
    if (n >= N) return;
    float xv[5];
#pragma unroll
    for (int k = 0; k < 5; k++) xv[k] = x[n * 5 + k];
#pragma unroll
    for (int j = 0; j < 32; j++) {
        float acc = sb[j];
#pragma unroll
        for (int k = 0; k < 5; k++) acc = fmaf(xv[k], sw[k * 32 + j], acc);
        g_h0[n * 32 + j] = fmaxf(acc, 0.f);
    }
}

// scatter conv1 + degree count (8 threads/edge, red.v4)
__global__ void scatter32(const int* __restrict__ src, const int* __restrict__ dst,
                          long long total) {
    long long idx = (long long)blockIdx.x * blockDim.x + threadIdx.x;
    if (idx >= total) return;
    int e = (int)(idx >> 3);
    int q = (int)(idx & 7);
    int s = __ldg(&src[e]);
    int d = __ldg(&dst[e]);
    float4 v = reinterpret_cast<const float4*>(g_h0)[s * 8 + q];
    red_add_v4(&g_agg32[d * 32 + q * 4], v);
    if (q == 0) red_add_f32(&g_cnt[d], 1.f);
}

// scatter conv2 (16 threads/edge, red.v4)
__global__ void scatter64(const int* __restrict__ src, const int* __restrict__ dst,
                          long long total) {
    long long idx = (long long)blockIdx.x * blockDim.x + threadIdx.x;
    if (idx >= total) return;
    int e = (int)(idx >> 4);
    int q = (int)(idx & 15);
    int s = __ldg(&src[e]);
    int d = __ldg(&dst[e]);
    float4 v = reinterpret_cast<const float4*>(g_h1)[s * 16 + q];
    red_add_v4(&g_agg64[d * 64 + q * 4], v);
}

// ---------------------------------------------------------------------------
// conv1 combine: h1 = relu(l2norm(mean_agg @ Wl + bl + h0 @ Wr))
// 512 threads (16 warps), 8 nodes/warp; inputs staged in smem, f32x2 FMA.
// dyn smem: swl[1024]f2 | swr[1024]f2 | sbias[32]f2 | sIn[16][512]f
__global__ __launch_bounds__(512)
void combine1(const float* __restrict__ wl, const float* __restrict__ bl,
              const float* __restrict__ wr, int N) {
    extern __shared__ char dyn[];
    float2* swl = (float2*)dyn;                 // 8192 B
    float2* swr = swl + 1024;                   // 8192 B
    float2* sbias = swr + 1024;                 // 256 B
    float* sIn = (float*)(sbias + 32);          // 16 * 2048 B

    int tid = threadIdx.x;
    for (int i = tid; i < 1024; i += 512) {
        int l = i >> 5, j = i & 31;
        swl[i] = make_float2(wl[l * 64 + j], wl[l * 64 + j + 32]);
        swr[i] = make_float2(wr[l * 64 + j], wr[l * 64 + j + 32]);
    }
    if (tid < 32) sbias[tid] = make_float2(bl[tid], bl[tid + 32]);
    __syncthreads();

    int warp = tid >> 5;
    int lane = tid & 31;
    int n0 = (blockIdx.x * 16 + warp) * 8;
    float* sA = sIn + warp * 512;
    float* sH = sA + 256;

    // stage inputs (mean applied here)
#pragma unroll
    for (int i = 0; i < 8; i++) {
        int n = n0 + i;
        float a = 0.f, h = 0.f;
        if (n < N) {
            float c = g_cnt[n];
            float ic = c > 0.f ? 1.f / c : 0.f;
            a = g_agg32[n * 32 + lane] * ic;
            h = g_h0[n * 32 + lane];
        }
        sA[i * 32 + lane] = a;
        sH[i * 32 + lane] = h;
    }
    __syncwarp();

    ull bias_p = ((const ull*)sbias)[lane];
    ull acc[8];
#pragma unroll
    for (int i = 0; i < 8; i++) acc[i] = bias_p;

    const ull* wlp = (const ull*)swl;
    const ull* wrp = (const ull*)swr;
#pragma unroll
    for (int lb = 0; lb < 8; lb++) {
        ull wl0 = wlp[(lb * 4 + 0) * 32 + lane];
        ull wl1 = wlp[(lb * 4 + 1) * 32 + lane];
        ull wl2 = wlp[(lb * 4 + 2) * 32 + lane];
        ull wl3 = wlp[(lb * 4 + 3) * 32 + lane];
        ull wr0 = wrp[(lb * 4 + 0) * 32 + lane];
        ull wr1 = wrp[(lb * 4 + 1) * 32 + lane];
        ull wr2 = wrp[(lb * 4 + 2) * 32 + lane];
        ull wr3 = wrp[(lb * 4 + 3) * 32 + lane];
#pragma unroll
        for (int i = 0; i < 8; i++) {
            float4 a4 = *(const float4*)&sA[i * 32 + lb * 4];
            float4 h4 = *(const float4*)&sH[i * 32 + lb * 4];
            acc[i] = ffma2(dup2(a4.x), wl0, acc[i]);
            acc[i] = ffma2(dup2(h4.x), wr0, acc[i]);
            acc[i] = ffma2(dup2(a4.y), wl1, acc[i]);
            acc[i] = ffma2(dup2(h4.y), wr1, acc[i]);
            acc[i] = ffma2(dup2(a4.z), wl2, acc[i]);
            acc[i] = ffma2(dup2(h4.z), wr2, acc[i]);
            acc[i] = ffma2(dup2(a4.w), wl3, acc[i]);
            acc[i] = ffma2(dup2(h4.w), wr3, acc[i]);
        }
    }

#pragma unroll
    for (int i = 0; i < 8; i++) {
        int n = n0 + i;
        if (n >= N) break;
        float2 o = unpack2(acc[i]);
        float ss = o.x * o.x + o.y * o.y;
#pragma unroll
        for (int off = 16; off > 0; off >>= 1) ss += __shfl_xor_sync(0xffffffffu, ss, off);
        float inv = 1.f / fmaxf(sqrtf(ss), 1e-12f);
        g_h1[n * 64 + lane] = fmaxf(o.x * inv, 0.f);
        g_h1[n * 64 + lane + 32] = fmaxf(o.y * inv, 0.f);
    }
}

// ---------------------------------------------------------------------------
// conv2 combine + pooling; 512 threads, 8 nodes/warp, staged inputs + f32x2
// dyn smem: swl[2048]f2 | swr[2048]f2 | sbias[32]f2 | sIn[16][1024]f
__global__ __launch_bounds__(512)
void combine2_pool(const int* __restrict__ batch,
                   const float* __restrict__ wl, const float* __restrict__ bl,
                   const float* __restrict__ wr, int N) {
    extern __shared__ char dyn[];
    float2* swl = (float2*)dyn;                 // 16384 B
    float2* swr = swl + 2048;                   // 16384 B
    float2* sbias = swr + 2048;                 // 256 B
    float* sIn = (float*)(sbias + 32);          // 16 * 4096 B

    int tid = threadIdx.x;
    for (int i = tid; i < 2048; i += 512) {
        int l = i >> 5, j = i & 31;
        swl[i] = make_float2(wl[l * 64 + j], wl[l * 64 + j + 32]);
        swr[i] = make_float2(wr[l * 64 + j], wr[l * 64 + j + 32]);
    }
    if (tid < 32) sbias[tid] = make_float2(bl[tid], bl[tid + 32]);
    __syncthreads();

    int warp = tid >> 5;
    int lane = tid & 31;
    int n0 = (blockIdx.x * 16 + warp) * 8;
    float* sA = sIn + warp * 1024;
    float* sH = sA + 512;

#pragma unroll
    for (int i = 0; i < 8; i++) {
        int n = n0 + i;
        float a0 = 0.f, a1 = 0.f, h0 = 0.f, h1 = 0.f;
        if (n < N) {
            float c = g_cnt[n];
            float ic = c > 0.f ? 1.f / c : 0.f;
            a0 = g_agg64[n * 64 + lane] * ic;
            a1 = g_agg64[n * 64 + 32 + lane] * ic;
            h0 = g_h1[n * 64 + lane];
            h1 = g_h1[n * 64 + 32 + lane];
        }
        sA[i * 64 + lane] = a0;
        sA[i * 64 + 32 + lane] = a1;
        sH[i * 64 + lane] = h0;
        sH[i * 64 + 32 + lane] = h1;
    }
    __syncwarp();

    ull bias_p = ((const ull*)sbias)[lane];
    ull acc[8];
#pragma unroll
    for (int i = 0; i < 8; i++) acc[i] = bias_p;

    const ull* wlp = (const ull*)swl;
    const ull* wrp = (const ull*)swr;
#pragma unroll
    for (int lb = 0; lb < 16; lb++) {
        ull wl0 = wlp[(lb * 4 + 0) * 32 + lane];
        ull wl1 = wlp[(lb * 4 + 1) * 32 + lane];
        ull wl2 = wlp[(lb * 4 + 2) * 32 + lane];
        ull wl3 = wlp[(lb * 4 + 3) * 32 + lane];
        ull wr0 = wrp[(lb * 4 + 0) * 32 + lane];
        ull wr1 = wrp[(lb * 4 + 1) * 32 + lane];
        ull wr2 = wrp[(lb * 4 + 2) * 32 + lane];
        ull wr3 = wrp[(lb * 4 + 3) * 32 + lane];
#pragma unroll
        for (int i = 0; i < 8; i++) {
            float4 a4 = *(const float4*)&sA[i * 64 + lb * 4];
            float4 h4 = *(const float4*)&sH[i * 64 + lb * 4];
            acc[i] = ffma2(dup2(a4.x), wl0, acc[i]);
            acc[i] = ffma2(dup2(h4.x), wr0, acc[i]);
            acc[i] = ffma2(dup2(a4.y), wl1, acc[i]);
            acc[i] = ffma2(dup2(h4.y), wr1, acc[i]);
            acc[i] = ffma2(dup2(a4.z), wl2, acc[i]);
            acc[i] = ffma2(dup2(h4.z), wr2, acc[i]);
            acc[i] = ffma2(dup2(a4.w), wl3, acc[i]);
            acc[i] = ffma2(dup2(h4.w), wr3, acc[i]);
        }
    }

#pragma unroll
    for (int i = 0; i < 8; i++) {
        int n = n0 + i;
        if (n >= N) break;
        float2 o = unpack2(acc[i]);
        float ss = o.x * o.x + o.y * o.y;
#pragma unroll
        for (int off = 16; off > 0; off >>= 1) ss += __shfl_xor_sync(0xffffffffu, ss, off);
        float inv = 1.f / fmaxf(sqrtf(ss), 1e-12f);
        float v0 = fmaxf(o.x * inv, 0.f);
        float v1 = fmaxf(o.y * inv, 0.f);
        int b = batch[n];
        red_add_f32(&g_gsum[b * 64 + lane], v0);
        red_add_f32(&g_gsum[b * 64 + 32 + lane], v1);
        if (lane == 0) red_add_f32(&g_gcnt[b], 1.f);
    }
}

// head MLP
__global__ void head_kernel(const float* __restrict__ p1w, const float* __restrict__ p1b,
                            const float* __restrict__ p2w, const float* __restrict__ p2b,
                            const float* __restrict__ ow, const float* __restrict__ ob,
                            float* __restrict__ out) {
    int g = blockIdx.x;
    int t = threadIdx.x;
    __shared__ float sg[64];
    __shared__ float sh[64];
    __shared__ float s2[16];

    float c = g_gcnt[g];
    float invc = 1.f / fmaxf(c, 1.f);
    sg[t] = g_gsum[g * 64 + t] * invc;
    __syncthreads();

    float acc = p1b[t];
#pragma unroll 8
    for (int k = 0; k < 64; k++) acc = fmaf(sg[k], p1w[k * 64 + t], acc);
    sh[t] = fmaxf(acc, 0.f);
    __syncthreads();

    if (t < 16) {
        float a = p2b[t];
#pragma unroll 8
        for (int k = 0; k < 64; k++) a = fmaf(sh[k], p2w[k * 16 + t], a);
        s2[t] = fmaxf(a, 0.f);
    }
    __syncthreads();

    if (t == 0) {
        float a = ob[0];
#pragma unroll
        for (int k = 0; k < 16; k++) a = fmaf(s2[k], ow[k], a);
        out[g] = a;
    }
}

// ---------------------------------------------------------------------------
extern "C" void kernel_launch(void* const* d_in, const int* in_sizes, int n_in,
                              void* d_out, int out_size) {
    const float* x = (const float*)d_in[0];
    const int* ei = (const int*)d_in[1];
    const int* batch = (const int*)d_in[2];

    int base = n_in - 14;
    const float* pre_w = (const float*)d_in[base + 0];
    const float* pre_b = (const float*)d_in[base + 1];
    const float* c1_wl = (const float*)d_in[base + 2];
    const float* c1_bl = (const float*)d_in[base + 3];
    const float* c1_wr = (const float*)d_in[base + 4];
    const float* c2_wl = (const float*)d_in[base + 5];
    const float* c2_bl = (const float*)d_in[base + 6];
    const float* c2_wr = (const float*)d_in[base + 7];
    const float* p1_w = (const float*)d_in[base + 8];
    const float* p1_b = (const float*)d_in[base + 9];
    const float* p2_w = (const float*)d_in[base + 10];
    const float* p2_b = (const float*)d_in[base + 11];
    const float* o_w = (const float*)d_in[base + 12];
    const float* o_b = (const float*)d_in[base + 13];

    int N = in_sizes[0] / 5;
    int E = in_sizes[1] / 2;
    const int* src = ei;
    const int* dst = ei + E;
    float* out = (float*)d_out;

    const int smem1 = 8192 + 8192 + 256 + 16 * 2048;          // 49408 B
    const int smem2 = 16384 + 16384 + 256 + 16 * 4096;        // 98560 B
    cudaFuncSetAttribute(combine1, cudaFuncAttributeMaxDynamicSharedMemorySize, smem1);
    cudaFuncSetAttribute(combine2_pool, cudaFuncAttributeMaxDynamicSharedMemorySize, smem2);

    zero_all<<<2048, 256>>>(N);
    pre_kernel<<<(N + 255) / 256, 256>>>(x, pre_w, pre_b, N);

    {
        long long total = (long long)E * 8;
        scatter32<<<(int)((total + 255) / 256), 256>>>(src, dst, total);
    }

    // 128 nodes per 512-thread block
    combine1<<<(N + 127) / 128, 512, smem1>>>(c1_wl, c1_bl, c1_wr, N);

    {
        long long total = (long long)E * 16;
        scatter64<<<(int)((total + 255) / 256), 256>>>(src, dst, total);
    }

    combine2_pool<<<(N + 127) / 128, 512, smem2>>>(batch, c2_wl, c2_bl, c2_wr, N);

    head_kernel<<<out_size, 64>>>(p1_w, p1_b, p2_w, p2_b, o_w, o_b, out);
}

// round 6
// speedup vs baseline: 2.7956x; 1.3492x over previous
#include <cuda_runtime.h>
#include <cuda_bf16.h>
#include <math.h>

// ---------------------------------------------------------------------------
// GNN_11957188952096: pre-linear -> SAGE(32->64) -> SAGE(64->64) -> pool -> MLP
// N=100000 nodes, E=1600000 edges, G=512 graphs
// CSR-by-dst gather aggregation (no float atomics in hot path)
// ---------------------------------------------------------------------------

#define MAXN 100000
#define MAXE 1600000
#define MAXG 512
#define SCAN_B 1024

__device__ float g_h0[MAXN * 32];     // pre-linear output
__device__ float g_h1[MAXN * 64];     // conv1 output
__device__ float g_agg32[MAXN * 32];  // conv1 neighbor means
__device__ float g_agg64[MAXN * 64];  // conv2 neighbor means
__device__ float g_gsum[MAXG * 64];   // pooled sums
__device__ float g_gcnt[MAXG];        // nodes per graph

__device__ int g_deg[MAXN];           // in-degree histogram
__device__ int g_scan[MAXN];          // inclusive scan (per-block)
__device__ int g_rowptr[MAXN];        // exclusive prefix = CSR row starts
__device__ int g_fill[MAXN];          // placement cursors
__device__ int g_adj[MAXE];           // CSR: src list grouped by dst
__device__ int g_bsum[256];           // scan block sums
__device__ int g_boff[256];           // scan block offsets

typedef unsigned long long ull;

__device__ __forceinline__ void red_add_f32(float* addr, float v) {
    asm volatile("red.global.add.f32 [%0], %1;"
                 :: "l"(addr), "f"(v) : "memory");
}
__device__ __forceinline__ ull ffma2(ull a, ull b, ull c) {
    ull d;
    asm("fma.rn.f32x2 %0, %1, %2, %3;" : "=l"(d) : "l"(a), "l"(b), "l"(c));
    return d;
}
__device__ __forceinline__ ull dup2(float x) {
    ull d;
    asm("mov.b64 %0, {%1, %1};" : "=l"(d) : "r"(__float_as_uint(x)));
    return d;
}
__device__ __forceinline__ float2 unpack2(ull v) {
    float2 r;
    asm("mov.b64 {%0, %1}, %2;" : "=f"(r.x), "=f"(r.y) : "l"(v));
    return r;
}

// ---------------------------------------------------------------------------
__global__ void zero_small(int N) {
    int i = blockIdx.x * blockDim.x + threadIdx.x;
    int stride = gridDim.x * blockDim.x;
    for (int k = i; k < N; k += stride) { g_deg[k] = 0; g_fill[k] = 0; }
    for (int k = i; k < MAXG * 64; k += stride) g_gsum[k] = 0.f;
    for (int k = i; k < MAXG; k += stride) g_gcnt[k] = 0.f;
}

// h0 = relu(x @ pre_w + pre_b)
__global__ void pre_kernel(const float* __restrict__ x,
                           const float* __restrict__ w,
                           const float* __restrict__ b, int N) {
    __shared__ float sw[5 * 32];
    __shared__ float sb[32];
    for (int i = threadIdx.x; i < 160; i += blockDim.x) sw[i] = w[i];
    if (threadIdx.x < 32) sb[threadIdx.x] = b[threadIdx.x];
    __syncthreads();
    int n = blockIdx.x * blockDim.x + threadIdx.x;
    if (n >= N) return;
    float xv[5];
#pragma unroll
    for (int k = 0; k < 5; k++) xv[k] = x[n * 5 + k];
#pragma unroll
    for (int j = 0; j < 32; j++) {
        float acc = sb[j];
#pragma unroll
        for (int k = 0; k < 5; k++) acc = fmaf(xv[k], sw[k * 32 + j], acc);
        g_h0[n * 32 + j] = fmaxf(acc, 0.f);
    }
}

// ---------------------------------------------------------------------------
// CSR construction
__global__ void hist_kernel(const int* __restrict__ dst, int E) {
    int e = blockIdx.x * blockDim.x + threadIdx.x;
    if (e < E) atomicAdd(&g_deg[dst[e]], 1);
}

// per-block inclusive scan (Hillis-Steele, 1024 elems/block)
__global__ void scan_s1(int N) {
    __shared__ int buf0[SCAN_B], buf1[SCAN_B];
    int t = threadIdx.x;
    int g = blockIdx.x * SCAN_B + t;
    buf0[t] = (g < N) ? g_deg[g] : 0;
    int* a = buf0; int* b = buf1;
#pragma unroll
    for (int off = 1; off < SCAN_B; off <<= 1) {
        __syncthreads();
        b[t] = (t >= off) ? a[t] + a[t - off] : a[t];
        int* tmp = a; a = b; b = tmp;
    }
    __syncthreads();
    if (g < N) g_scan[g] = a[t];
    if (t == SCAN_B - 1) g_bsum[blockIdx.x] = a[t];
}

__global__ void scan_s2(int nb) {
    if (threadIdx.x == 0 && blockIdx.x == 0) {
        int run = 0;
        for (int i = 0; i < nb; i++) { g_boff[i] = run; run += g_bsum[i]; }
    }
}

__global__ void scan_s3(int N) {
    int g = blockIdx.x * SCAN_B + threadIdx.x;
    if (g < N) g_rowptr[g] = g_scan[g] - g_deg[g] + g_boff[blockIdx.x];
}

__global__ void place_kernel(const int* __restrict__ src, const int* __restrict__ dst,
                             int E) {
    int e = blockIdx.x * blockDim.x + threadIdx.x;
    if (e >= E) return;
    int d = dst[e];
    int pos = g_rowptr[d] + atomicAdd(&g_fill[d], 1);
    g_adj[pos] = src[e];
}

// ---------------------------------------------------------------------------
// gather aggregation conv1: 8 lanes x float4 per node (4 nodes/warp)
// writes MEAN directly into g_agg32
__global__ void agg1(int N) {
    int gw = (blockIdx.x * blockDim.x + threadIdx.x) >> 5;
    int lane = threadIdx.x & 31;
    int sub = lane >> 3, sl = lane & 7;
    int n = gw * 4 + sub;
    if (n >= N) return;
    int start = g_rowptr[n];
    int deg = g_deg[n];
    const float4* h0 = (const float4*)g_h0;
    float4 acc = make_float4(0.f, 0.f, 0.f, 0.f);
    int k = 0;
    for (; k + 2 <= deg; k += 2) {
        int s0 = __ldg(&g_adj[start + k]);
        int s1 = __ldg(&g_adj[start + k + 1]);
        float4 v0 = h0[s0 * 8 + sl];
        float4 v1 = h0[s1 * 8 + sl];
        acc.x += v0.x + v1.x; acc.y += v0.y + v1.y;
        acc.z += v0.z + v1.z; acc.w += v0.w + v1.w;
    }
    if (k < deg) {
        int s0 = __ldg(&g_adj[start + k]);
        float4 v0 = h0[s0 * 8 + sl];
        acc.x += v0.x; acc.y += v0.y; acc.z += v0.z; acc.w += v0.w;
    }
    float inv = deg > 0 ? 1.f / (float)deg : 0.f;
    ((float4*)g_agg32)[n * 8 + sl] =
        make_float4(acc.x * inv, acc.y * inv, acc.z * inv, acc.w * inv);
}

// gather aggregation conv2: 16 lanes x float4 per node (2 nodes/warp)
__global__ void agg2(int N) {
    int gw = (blockIdx.x * blockDim.x + threadIdx.x) >> 5;
    int lane = threadIdx.x & 31;
    int sub = lane >> 4, sl = lane & 15;
    int n = gw * 2 + sub;
    if (n >= N) return;
    int start = g_rowptr[n];
    int deg = g_deg[n];
    const float4* h1 = (const float4*)g_h1;
    float4 acc = make_float4(0.f, 0.f, 0.f, 0.f);
    int k = 0;
    for (; k + 2 <= deg; k += 2) {
        int s0 = __ldg(&g_adj[start + k]);
        int s1 = __ldg(&g_adj[start + k + 1]);
        float4 v0 = h1[s0 * 16 + sl];
        float4 v1 = h1[s1 * 16 + sl];
        acc.x += v0.x + v1.x; acc.y += v0.y + v1.y;
        acc.z += v0.z + v1.z; acc.w += v0.w + v1.w;
    }
    if (k < deg) {
        int s0 = __ldg(&g_adj[start + k]);
        float4 v0 = h1[s0 * 16 + sl];
        acc.x += v0.x; acc.y += v0.y; acc.z += v0.z; acc.w += v0.w;
    }
    float inv = deg > 0 ? 1.f / (float)deg : 0.f;
    ((float4*)g_agg64)[n * 16 + sl] =
        make_float4(acc.x * inv, acc.y * inv, acc.z * inv, acc.w * inv);
}

// ---------------------------------------------------------------------------
// conv1 combine: h1 = relu(l2norm(agg32 @ Wl + bl + h0 @ Wr))
// 512 threads, min 2 blocks/SM; 8 nodes/warp; staged inputs; f32x2 FMA
__global__ __launch_bounds__(512, 2)
void combine1(const float* __restrict__ wl, const float* __restrict__ bl,
              const float* __restrict__ wr, int N) {
    extern __shared__ char dyn[];
    float2* swl = (float2*)dyn;                 // 8192 B
    float2* swr = swl + 1024;                   // 8192 B
    float2* sbias = swr + 1024;                 // 256 B
    float* sIn = (float*)(sbias + 32);          // 16 * 2048 B

    int tid = threadIdx.x;
    for (int i = tid; i < 1024; i += 512) {
        int l = i >> 5, j = i & 31;
        swl[i] = make_float2(wl[l * 64 + j], wl[l * 64 + j + 32]);
        swr[i] = make_float2(wr[l * 64 + j], wr[l * 64 + j + 32]);
    }
    if (tid < 32) sbias[tid] = make_float2(bl[tid], bl[tid + 32]);
    __syncthreads();

    int warp = tid >> 5;
    int lane = tid & 31;
    int n0 = (blockIdx.x * 16 + warp) * 8;
    float* sA = sIn + warp * 512;
    float* sH = sA + 256;

#pragma unroll
    for (int i = 0; i < 8; i++) {
        int n = n0 + i;
        float a = 0.f, h = 0.f;
        if (n < N) {
            a = g_agg32[n * 32 + lane];
            h = g_h0[n * 32 + lane];
        }
        sA[i * 32 + lane] = a;
        sH[i * 32 + lane] = h;
    }
    __syncwarp();

    ull bias_p = ((const ull*)sbias)[lane];
    ull acc[8];
#pragma unroll
    for (int i = 0; i < 8; i++) acc[i] = bias_p;

    const ull* wlp = (const ull*)swl;
    const ull* wrp = (const ull*)swr;
#pragma unroll
    for (int lb = 0; lb < 8; lb++) {
        ull wl0 = wlp[(lb * 4 + 0) * 32 + lane];
        ull wl1 = wlp[(lb * 4 + 1) * 32 + lane];
        ull wl2 = wlp[(lb * 4 + 2) * 32 + lane];
        ull wl3 = wlp[(lb * 4 + 3) * 32 + lane];
        ull wr0 = wrp[(lb * 4 + 0) * 32 + lane];
        ull wr1 = wrp[(lb * 4 + 1) * 32 + lane];
        ull wr2 = wrp[(lb * 4 + 2) * 32 + lane];
        ull wr3 = wrp[(lb * 4 + 3) * 32 + lane];
#pragma unroll
        for (int i = 0; i < 8; i++) {
            float4 a4 = *(const float4*)&sA[i * 32 + lb * 4];
            float4 h4 = *(const float4*)&sH[i * 32 + lb * 4];
            acc[i] = ffma2(dup2(a4.x), wl0, acc[i]);
            acc[i] = ffma2(dup2(h4.x), wr0, acc[i]);
            acc[i] = ffma2(dup2(a4.y), wl1, acc[i]);
            acc[i] = ffma2(dup2(h4.y), wr1, acc[i]);
            acc[i] = ffma2(dup2(a4.z), wl2, acc[i]);
            acc[i] = ffma2(dup2(h4.z), wr2, acc[i]);
            acc[i] = ffma2(dup2(a4.w), wl3, acc[i]);
            acc[i] = ffma2(dup2(h4.w), wr3, acc[i]);
        }
    }

#pragma unroll
    for (int i = 0; i < 8; i++) {
        int n = n0 + i;
        if (n >= N) break;
        float2 o = unpack2(acc[i]);
        float ss = o.x * o.x + o.y * o.y;
#pragma unroll
        for (int off = 16; off > 0; off >>= 1) ss += __shfl_xor_sync(0xffffffffu, ss, off);
        float inv = 1.f / fmaxf(sqrtf(ss), 1e-12f);
        g_h1[n * 64 + lane] = fmaxf(o.x * inv, 0.f);
        g_h1[n * 64 + lane + 32] = fmaxf(o.y * inv, 0.f);
    }
}

// ---------------------------------------------------------------------------
// conv2 combine + pooling; 512 threads, min 2 blocks/SM
__global__ __launch_bounds__(512, 2)
void combine2_pool(const int* __restrict__ batch,
                   const float* __restrict__ wl, const float* __restrict__ bl,
                   const float* __restrict__ wr, int N) {
    extern __shared__ char dyn[];
    float2* swl = (float2*)dyn;                 // 16384 B
    float2* swr = swl + 2048;                   // 16384 B
    float2* sbias = swr + 2048;                 // 256 B
    float* sIn = (float*)(sbias + 32);          // 16 * 4096 B

    int tid = threadIdx.x;
    for (int i = tid; i < 2048; i += 512) {
        int l = i >> 5, j = i & 31;
        swl[i] = make_float2(wl[l * 64 + j], wl[l * 64 + j + 32]);
        swr[i] = make_float2(wr[l * 64 + j], wr[l * 64 + j + 32]);
    }
    if (tid < 32) sbias[tid] = make_float2(bl[tid], bl[tid + 32]);
    __syncthreads();

    int warp = tid >> 5;
    int lane = tid & 31;
    int n0 = (blockIdx.x * 16 + warp) * 8;
    float* sA = sIn + warp * 1024;
    float* sH = sA + 512;

#pragma unroll
    for (int i = 0; i < 8; i++) {
        int n = n0 + i;
        float a0 = 0.f, a1 = 0.f, h0 = 0.f, h1 = 0.f;
        if (n < N) {
            a0 = g_agg64[n * 64 + lane];
            a1 = g_agg64[n * 64 + 32 + lane];
            h0 = g_h1[n * 64 + lane];
            h1 = g_h1[n * 64 + 32 + lane];
        }
        sA[i * 64 + lane] = a0;
        sA[i * 64 + 32 + lane] = a1;
        sH[i * 64 + lane] = h0;
        sH[i * 64 + 32 + lane] = h1;
    }
    __syncwarp();

    ull bias_p = ((const ull*)sbias)[lane];
    ull acc[8];
#pragma unroll
    for (int i = 0; i < 8; i++) acc[i] = bias_p;

    const ull* wlp = (const ull*)swl;
    const ull* wrp = (const ull*)swr;
#pragma unroll
    for (int lb = 0; lb < 16; lb++) {
        ull wl0 = wlp[(lb * 4 + 0) * 32 + lane];
        ull wl1 = wlp[(lb * 4 + 1) * 32 + lane];
        ull wl2 = wlp[(lb * 4 + 2) * 32 + lane];
        ull wl3 = wlp[(lb * 4 + 3) * 32 + lane];
        ull wr0 = wrp[(lb * 4 + 0) * 32 + lane];
        ull wr1 = wrp[(lb * 4 + 1) * 32 + lane];
        ull wr2 = wrp[(lb * 4 + 2) * 32 + lane];
        ull wr3 = wrp[(lb * 4 + 3) * 32 + lane];
#pragma unroll
        for (int i = 0; i < 8; i++) {
            float4 a4 = *(const float4*)&sA[i * 64 + lb * 4];
            float4 h4 = *(const float4*)&sH[i * 64 + lb * 4];
            acc[i] = ffma2(dup2(a4.x), wl0, acc[i]);
            acc[i] = ffma2(dup2(h4.x), wr0, acc[i]);
            acc[i] = ffma2(dup2(a4.y), wl1, acc[i]);
            acc[i] = ffma2(dup2(h4.y), wr1, acc[i]);
            acc[i] = ffma2(dup2(a4.z), wl2, acc[i]);
            acc[i] = ffma2(dup2(h4.z), wr2, acc[i]);
            acc[i] = ffma2(dup2(a4.w), wl3, acc[i]);
            acc[i] = ffma2(dup2(h4.w), wr3, acc[i]);
        }
    }

#pragma unroll
    for (int i = 0; i < 8; i++) {
        int n = n0 + i;
        if (n >= N) break;
        float2 o = unpack2(acc[i]);
        float ss = o.x * o.x + o.y * o.y;
#pragma unroll
        for (int off = 16; off > 0; off >>= 1) ss += __shfl_xor_sync(0xffffffffu, ss, off);
        float inv = 1.f / fmaxf(sqrtf(ss), 1e-12f);
        float v0 = fmaxf(o.x * inv, 0.f);
        float v1 = fmaxf(o.y * inv, 0.f);
        int b = batch[n];
        red_add_f32(&g_gsum[b * 64 + lane], v0);
        red_add_f32(&g_gsum[b * 64 + 32 + lane], v1);
        if (lane == 0) red_add_f32(&g_gcnt[b], 1.f);
    }
}

// head MLP
__global__ void head_kernel(const float* __restrict__ p1w, const float* __restrict__ p1b,
                            const float* __restrict__ p2w, const float* __restrict__ p2b,
                            const float* __restrict__ ow, const float* __restrict__ ob,
                            float* __restrict__ out) {
    int g = blockIdx.x;
    int t = threadIdx.x;
    __shared__ float sg[64];
    __shared__ float sh[64];
    __shared__ float s2[16];

    float c = g_gcnt[g];
    float invc = 1.f / fmaxf(c, 1.f);
    sg[t] = g_gsum[g * 64 + t] * invc;
    __syncthreads();

    float acc = p1b[t];
#pragma unroll 8
    for (int k = 0; k < 64; k++) acc = fmaf(sg[k], p1w[k * 64 + t], acc);
    sh[t] = fmaxf(acc, 0.f);
    __syncthreads();

    if (t < 16) {
        float a = p2b[t];
#pragma unroll 8
        for (int k = 0; k < 64; k++) a = fmaf(sh[k], p2w[k * 16 + t], a);
        s2[t] = fmaxf(a, 0.f);
    }
    __syncthreads();

    if (t == 0) {
        float a = ob[0];
#pragma unroll
        for (int k = 0; k < 16; k++) a = fmaf(s2[k], ow[k], a);
        out[g] = a;
    }
}

// ---------------------------------------------------------------------------
extern "C" void kernel_launch(void* const* d_in, const int* in_sizes, int n_in,
                              void* d_out, int out_size) {
    const float* x = (const float*)d_in[0];
    const int* ei = (const int*)d_in[1];
    const int* batch = (const int*)d_in[2];

    int base = n_in - 14;
    const float* pre_w = (const float*)d_in[base + 0];
    const float* pre_b = (const float*)d_in[base + 1];
    const float* c1_wl = (const float*)d_in[base + 2];
    const float* c1_bl = (const float*)d_in[base + 3];
    const float* c1_wr = (const float*)d_in[base + 4];
    const float* c2_wl = (const float*)d_in[base + 5];
    const float* c2_bl = (const float*)d_in[base + 6];
    const float* c2_wr = (const float*)d_in[base + 7];
    const float* p1_w = (const float*)d_in[base + 8];
    const float* p1_b = (const float*)d_in[base + 9];
    const float* p2_w = (const float*)d_in[base + 10];
    const float* p2_b = (const float*)d_in[base + 11];
    const float* o_w = (const float*)d_in[base + 12];
    const float* o_b = (const float*)d_in[base + 13];

    int N = in_sizes[0] / 5;
    int E = in_sizes[1] / 2;
    const int* src = ei;
    const int* dst = ei + E;
    float* out = (float*)d_out;

    const int smem1 = 8192 + 8192 + 256 + 16 * 2048;          // 49408 B
    const int smem2 = 16384 + 16384 + 256 + 16 * 4096;        // 98560 B
    cudaFuncSetAttribute(combine1, cudaFuncAttributeMaxDynamicSharedMemorySize, smem1);
    cudaFuncSetAttribute(combine2_pool, cudaFuncAttributeMaxDynamicSharedMemorySize, smem2);

    int nb = (N + SCAN_B - 1) / SCAN_B;

    zero_small<<<512, 256>>>(N);
    pre_kernel<<<(N + 255) / 256, 256>>>(x, pre_w, pre_b, N);

    // CSR build (shared by both convs)
    hist_kernel<<<(E + 255) / 256, 256>>>(dst, E);
    scan_s1<<<nb, SCAN_B>>>(N);
    scan_s2<<<1, 32>>>(nb);
    scan_s3<<<nb, SCAN_B>>>(N);
    place_kernel<<<(E + 255) / 256, 256>>>(src, dst, E);

    // conv1: gather-agg then combine
    agg1<<<(N + 31) / 32, 256>>>(N);            // 4 nodes/warp, 8 warps/block
    combine1<<<(N + 127) / 128, 512, smem1>>>(c1_wl, c1_bl, c1_wr, N);

    // conv2: gather-agg then combine+pool
    agg2<<<(N + 15) / 16, 256>>>(N);            // 2 nodes/warp, 8 warps/block
    combine2_pool<<<(N + 127) / 128, 512, smem2>>>(batch, c2_wl, c2_bl, c2_wr, N);

    head_kernel<<<out_size, 64>>>(p1_w, p1_b, p2_w, p2_b, o_w, o_b, out);
}